// round 13
// baseline (speedup 1.0000x reference)
#include <cuda_runtime.h>
#include <cuda_bf16.h>
#include <cstdint>

// Shapes
#define BATCH 1024
#define CIN   512
#define KDIM  768            // contraction: c2 = j*256 + l
#define NDIM  1536           // n = k*512 + i
#define MDIM  (BATCH * 49)   // 50176 = b*49 + n*7 + w

// Quantization: v ~= QA*q1 + QB*q2,  QB = QA/254 (residual in [-QA/2, QA/2])
#define QA (10.0f / 127.0f)     // S bound: |S| <= ~10 (N(0,sqrt(2)))
#define QB (QA / 254.0f)
#define QG (5.5f / 127.0f)      // W bound: |W| <= ~5.5 (N(0,1))
#define QD (QG / 254.0f)

// Scratch (static __device__ — no allocations allowed)
__device__ __align__(1024) signed char g_S1[(size_t)MDIM * KDIM];   // 38.5 MB
__device__ __align__(1024) signed char g_S2[(size_t)MDIM * KDIM];   // 38.5 MB
__device__ __align__(1024) signed char g_W1[(size_t)NDIM * KDIM];   // [N][K], 1.2 MB
__device__ __align__(1024) signed char g_W2[(size_t)NDIM * KDIM];
__device__ __align__(1024) float g_G[(size_t)MDIM * NDIM];          // 308 MB

// ---------------------------------------------------------------------------
// PTX helpers — compute_103-safe (cp.async, ldmatrix, imma)
// ---------------------------------------------------------------------------
__device__ __forceinline__ uint32_t smem_u32(const void* p) {
    uint32_t a;
    asm("{ .reg .u64 t; cvta.to.shared.u64 t, %1; cvt.u32.u64 %0, t; }" : "=r"(a) : "l"(p));
    return a;
}
#define CP16(dst, src) \
    asm volatile("cp.async.cg.shared.global [%0], [%1], 16;" :: "r"(dst), "l"(src))
#define CP_COMMIT() asm volatile("cp.async.commit_group;" ::: "memory")
#define CP_WAIT1()  asm volatile("cp.async.wait_group 1;" ::: "memory")

#define LDSM_X4(R, addr)                                                      \
    asm volatile("ldmatrix.sync.aligned.m8n8.x4.shared.b16 {%0,%1,%2,%3}, [%4];" \
        : "=r"((R)[0]), "=r"((R)[1]), "=r"((R)[2]), "=r"((R)[3]) : "r"(addr))

#define IMMA16832(D, A, B0, B1)                                               \
    asm volatile("mma.sync.aligned.m16n8k32.row.col.s32.s8.s8.s32 "           \
        "{%0,%1,%2,%3}, {%4,%5,%6,%7}, {%8,%9}, {%0,%1,%2,%3};"               \
        : "+r"((D)[0]), "+r"((D)[1]), "+r"((D)[2]), "+r"((D)[3])              \
        : "r"((A)[0]), "r"((A)[1]), "r"((A)[2]), "r"((A)[3]),                 \
          "r"(B0), "r"(B1))

struct QPair { signed char q1, q2; };

__device__ __forceinline__ QPair quant2(float v, float inv_a, float a, float inv_b) {
    int q1 = __float2int_rn(v * inv_a);
    q1 = max(-127, min(127, q1));
    float r = v - a * (float)q1;
    int q2 = __float2int_rn(r * inv_b);
    q2 = max(-127, min(127, q2));
    QPair c; c.q1 = (signed char)q1; c.q2 = (signed char)q2;
    return c;
}

// ---------------------------------------------------------------------------
// W quant, layout [N=1536][K=768]: g_W{1,2}[n*768 + c2] = quant(W[l,j,k,i])
//   n = k*512 + i, c2 = j*256 + l
// ---------------------------------------------------------------------------
__global__ void build_w_k(const float* __restrict__ W) {
    int idx4 = blockIdx.x * 256 + threadIdx.x;      // over NDIM*192
    if (idx4 >= NDIM * (KDIM / 4)) return;
    int n  = idx4 / (KDIM / 4);
    int c2 = (idx4 - n * (KDIM / 4)) * 4;
    int k = n >> 9, i = n & 511;
    int j = c2 >> 8, l0 = c2 & 255;
    uint32_t o1 = 0, o2 = 0;
#pragma unroll
    for (int q = 0; q < 4; q++) {
        float v = W[((((l0 + q) * 3 + j) * 3 + k) << 9) + i];
        QPair c = quant2(v, 1.f / QG, QG, 1.f / QD);
        o1 |= (uint32_t)(unsigned char)c.q1 << (q * 8);
        o2 |= (uint32_t)(unsigned char)c.q2 << (q * 8);
    }
    ((uint32_t*)g_W1)[idx4] = o1;
    ((uint32_t*)g_W2)[idx4] = o2;
}

// ---------------------------------------------------------------------------
// S quant: S[b][n][w][j*256+l] = xz(b,256+l,(n+6)%7+j-1,w) + xz(b,l,n+j-1,w)
// ---------------------------------------------------------------------------
__global__ void build_s_k(const float* __restrict__ x) {
    extern __shared__ float sx[];  // 512*49 floats
    int b = blockIdx.x;
    const float4* xb = (const float4*)(x + (size_t)b * (CIN * 49));
    for (int i = threadIdx.x; i < CIN * 49 / 4; i += blockDim.x)
        ((float4*)sx)[i] = xb[i];
    __syncthreads();

    size_t base4 = (size_t)b * (49 * KDIM / 4);
    for (int e4 = threadIdx.x; e4 < 49 * (KDIM / 4); e4 += blockDim.x) {
        int nw = e4 / (KDIM / 4);
        int c2 = (e4 - nw * (KDIM / 4)) * 4;
        int n = nw / 7, w = nw - n * 7;
        int j = c2 >> 8, l0 = c2 & 255;
        int r0 = n + j - 1;
        int n2 = n + 6; if (n2 >= 7) n2 -= 7;
        int r1 = n2 + j - 1;
        bool g0 = (unsigned)r0 < 7u, g1 = (unsigned)r1 < 7u;
        uint32_t o1 = 0, o2 = 0;
#pragma unroll
        for (int q = 0; q < 4; q++) {
            int l = l0 + q;
            float v = 0.f;
            if (g0) v += sx[l * 49 + r0 * 7 + w];
            if (g1) v += sx[(256 + l) * 49 + r1 * 7 + w];
            QPair c = quant2(v, 1.f / QA, QA, 1.f / QB);
            o1 |= (uint32_t)(unsigned char)c.q1 << (q * 8);
            o2 |= (uint32_t)(unsigned char)c.q2 << (q * 8);
        }
        ((uint32_t*)g_S1)[base4 + e4] = o1;
        ((uint32_t*)g_S2)[base4 + e4] = o2;
    }
}

// ---------------------------------------------------------------------------
// INT8 GEMM via mma.sync.m16n8k32.s8 (2x bf16 rate, exact s32 accum).
// G = QA*QG * (S1*W1 + (S1*W2 + S2*W1)/254)     [S2*W2 dropped, ~2e-4 rel]
// CTA 128x128, BK=64, 36 chunks (3 segs x 12), 3-stage cp.async, 1 sync/chunk.
// 16 warps 4x4; warp tile 32x32. Two s32 accumulator sets (seg0 / seg1+2).
// SMEM/stage: A 128 rows x 80B + B 128 rows x 80B = 20480B; x3 = 61440B.
// ---------------------------------------------------------------------------
#define LDS_S 80
#define STG_B 20480
#define NCHUNK 36

__global__ __launch_bounds__(512) void gemm_k() {
    extern __shared__ __align__(128) char smem[];
    const uint32_t sb = smem_u32(smem);
    const int tid  = threadIdx.x;
    const int wid  = tid >> 5;
    const int lane = tid & 31;
    const int wm = wid & 3;          // m offset *32
    const int wn = wid >> 2;         // n offset *32

    const size_t m0 = (size_t)blockIdx.y * 128;
    const int    n0 = blockIdx.x * 128;

    int acc1[2][4][4], acc2[2][4][4];
#pragma unroll
    for (int mt = 0; mt < 2; mt++)
#pragma unroll
        for (int nt = 0; nt < 4; nt++)
#pragma unroll
            for (int q = 0; q < 4; q++) { acc1[mt][nt][q] = 0; acc2[mt][nt][q] = 0; }

    const int ar = tid >> 2, acb = (tid & 3) << 4;   // cp.async row / 16B col

    auto issue = [&](int kc) {
        int seg = kc / 12, kk = kc - seg * 12;
        const signed char* As = ((seg < 2) ? g_S1 : g_S2) + m0 * KDIM;
        const signed char* Bs = ((seg == 1) ? g_W2 : g_W1) + (size_t)n0 * KDIM;
        const uint32_t st = sb + (kc % 3) * STG_B;
        const int k0 = kk * 64;
        CP16(st + ar * LDS_S + acb,          As + (size_t)ar * KDIM + k0 + acb);
        CP16(st + 10240 + ar * LDS_S + acb,  Bs + (size_t)ar * KDIM + k0 + acb);
    };

    issue(0); CP_COMMIT();
    issue(1); CP_COMMIT();

    // ldmatrix addresses (byte units)
    const uint32_t a_off = (uint32_t)(wm * 32 + (lane & 15)) * LDS_S + ((lane >> 4) << 4);
    const uint32_t b_off = 10240 +
        (uint32_t)(wn * 32 + ((lane >> 4) << 3) + (lane & 7)) * LDS_S + (((lane >> 3) & 1) << 4);

    for (int kc = 0; kc < NCHUNK; kc++) {
        CP_WAIT1();
        __syncthreads();
        if (kc + 2 < NCHUNK) issue(kc + 2);
        CP_COMMIT();                            // uniform group numbering

        const uint32_t st = sb + (kc % 3) * STG_B;
        const bool first = (kc < 12);

#pragma unroll
        for (int ks = 0; ks < 2; ks++) {
            uint32_t af[2][4], bf[2][4];
#pragma unroll
            for (int mt = 0; mt < 2; mt++)
                LDSM_X4(af[mt], st + a_off + mt * (16 * LDS_S) + ks * 32);
#pragma unroll
            for (int p = 0; p < 2; p++)
                LDSM_X4(bf[p], st + b_off + p * (16 * LDS_S) + ks * 32);
            if (first) {
#pragma unroll
                for (int mt = 0; mt < 2; mt++)
#pragma unroll
                    for (int nt = 0; nt < 4; nt++)
                        IMMA16832(acc1[mt][nt], af[mt],
                                  bf[nt >> 1][(nt & 1) * 2],
                                  bf[nt >> 1][(nt & 1) * 2 + 1]);
            } else {
#pragma unroll
                for (int mt = 0; mt < 2; mt++)
#pragma unroll
                    for (int nt = 0; nt < 4; nt++)
                        IMMA16832(acc2[mt][nt], af[mt],
                                  bf[nt >> 1][(nt & 1) * 2],
                                  bf[nt >> 1][(nt & 1) * 2 + 1]);
            }
        }
    }

    // Writeback: out = s0*acc1 + (s0/254)*acc2
    const float s0 = QA * QG;
    const float s1 = s0 / 254.0f;
    const int g = lane >> 2, tig = lane & 3;
#pragma unroll
    for (int mt = 0; mt < 2; mt++) {
        size_t mrow = m0 + wm * 32 + mt * 16 + g;
        float* c0 = g_G + mrow * NDIM + n0 + wn * 32 + tig * 2;
        float* c1 = c0 + 8 * NDIM;
#pragma unroll
        for (int nt = 0; nt < 4; nt++) {
            *(float2*)(c0 + nt * 8) = make_float2(
                s0 * (float)acc1[mt][nt][0] + s1 * (float)acc2[mt][nt][0],
                s0 * (float)acc1[mt][nt][1] + s1 * (float)acc2[mt][nt][1]);
            *(float2*)(c1 + nt * 8) = make_float2(
                s0 * (float)acc1[mt][nt][2] + s1 * (float)acc2[mt][nt][2],
                s0 * (float)acc1[mt][nt][3] + s1 * (float)acc2[mt][nt][3]);
        }
    }
}

// ---------------------------------------------------------------------------
// out[b,i,n,p] = sum_k [0 <= p+k-1 < 7] * G[b, n, (p+k+5)%7][k*512+i]
// ---------------------------------------------------------------------------
__global__ void epilogue_k(float* __restrict__ out) {
    __shared__ float sg[7 * NDIM];  // 43 KB
    int b = blockIdx.x / 7;
    int n = blockIdx.x % 7;
    const float4* Gb = (const float4*)(g_G + (size_t)(b * 49 + n * 7) * NDIM);
    for (int i = threadIdx.x; i < 7 * NDIM / 4; i += blockDim.x)
        ((float4*)sg)[i] = Gb[i];
    __syncthreads();

    for (int e = threadIdx.x; e < 512 * 7; e += blockDim.x) {
        int i = e / 7;
        int p = e - i * 7;
        float v = 0.f;
#pragma unroll
        for (int k = 0; k < 3; k++) {
            int q = p + k - 1;
            if ((unsigned)q < 7u) {
                int w = p + k + 5; if (w >= 7) w -= 7;
                v += sg[w * NDIM + (k << 9) + i];
            }
        }
        out[(((size_t)b * 512 + i) * 7 + n) * 7 + p] = v;
    }
}

// ---------------------------------------------------------------------------
extern "C" void kernel_launch(void* const* d_in, const int* in_sizes, int n_in,
                              void* d_out, int out_size) {
    const float* x = (const float*)d_in[0];   // (1024,512,7,7)
    const float* W = (const float*)d_in[1];   // (256,3,3,512)
    float* out = (float*)d_out;               // (1024,512,7,7)

    cudaFuncSetAttribute(build_s_k, cudaFuncAttributeMaxDynamicSharedMemorySize,
                         CIN * 49 * 4);
    cudaFuncSetAttribute(gemm_k, cudaFuncAttributeMaxDynamicSharedMemorySize,
                         3 * STG_B);

    build_w_k<<<(NDIM * (KDIM / 4) + 255) / 256, 256>>>(W);
    build_s_k<<<BATCH, 256, CIN * 49 * 4>>>(x);

    dim3 grid(NDIM / 128, MDIM / 128);  // (12, 392)
    gemm_k<<<grid, 512, 3 * STG_B>>>();

    epilogue_k<<<BATCH * 7, 256>>>(out);
}

// round 15
// speedup vs baseline: 3.6191x; 3.6191x over previous
#include <cuda_runtime.h>
#include <cuda_fp16.h>
#include <cstdint>

// Shapes
#define BATCH 1024
#define CIN   512
#define KDIM  768            // contraction: c2 = j*256 + l
#define NDIM  1536           // n = k*512 + i
#define MDIM  (BATCH * 49)   // 50176 = b*49 + n*7 + w

// Scratch (static __device__ — no allocations allowed)
__device__ __align__(1024) __half g_Shi[(size_t)MDIM * KDIM];   // 77 MB
__device__ __align__(1024) __half g_Whi[(size_t)KDIM * NDIM];   // [K][N], 2.4 MB
__device__ __align__(1024) __half g_Wlo[(size_t)KDIM * NDIM];
__device__ __align__(1024) float  g_G[(size_t)MDIM * NDIM];     // 308 MB

// ---------------------------------------------------------------------------
// PTX helpers — compute_103-safe (cp.async, ldmatrix, mma.sync f16)
// ---------------------------------------------------------------------------
__device__ __forceinline__ uint32_t smem_u32(const void* p) {
    uint32_t a;
    asm("{ .reg .u64 t; cvta.to.shared.u64 t, %1; cvt.u32.u64 %0, t; }" : "=r"(a) : "l"(p));
    return a;
}
#define CP16(dst, src) \
    asm volatile("cp.async.cg.shared.global [%0], [%1], 16;" :: "r"(dst), "l"(src))
#define CP_COMMIT() asm volatile("cp.async.commit_group;" ::: "memory")
#define CP_WAIT1()  asm volatile("cp.async.wait_group 1;" ::: "memory")

#define LDSM_X4(R, addr)                                                      \
    asm volatile("ldmatrix.sync.aligned.m8n8.x4.shared.b16 {%0,%1,%2,%3}, [%4];" \
        : "=r"((R)[0]), "=r"((R)[1]), "=r"((R)[2]), "=r"((R)[3]) : "r"(addr))
#define LDSM_X4_T(R, addr)                                                    \
    asm volatile("ldmatrix.sync.aligned.m8n8.x4.trans.shared.b16 {%0,%1,%2,%3}, [%4];" \
        : "=r"((R)[0]), "=r"((R)[1]), "=r"((R)[2]), "=r"((R)[3]) : "r"(addr))

#define MMA16816(D, A, B0, B1)                                                \
    asm volatile("mma.sync.aligned.m16n8k16.row.col.f32.f16.f16.f32 "         \
        "{%0,%1,%2,%3}, {%4,%5,%6,%7}, {%8,%9}, {%0,%1,%2,%3};"               \
        : "+f"((D)[0]), "+f"((D)[1]), "+f"((D)[2]), "+f"((D)[3])              \
        : "r"((A)[0]), "r"((A)[1]), "r"((A)[2]), "r"((A)[3]),                 \
          "r"(B0), "r"(B1))

// ---------------------------------------------------------------------------
// W hi/lo, layout [K=768][N=1536]: g_W{hi,lo}[c2*1536 + n] = split(W[l,j,k,i])
//   n = k*512 + i, c2 = j*256 + l
// ---------------------------------------------------------------------------
__global__ void build_w_k(const float* __restrict__ W) {
    int idx = blockIdx.x * 256 + threadIdx.x;
    if (idx >= KDIM * NDIM) return;
    int n  = idx % NDIM;
    int c2 = idx / NDIM;
    int k = n >> 9, i = n & 511;
    int j = c2 >> 8, l = c2 & 255;
    float v = W[(((l * 3 + j) * 3 + k) << 9) + i];
    __half hi = __float2half_rn(v);
    __half lo = __float2half_rn(v - __half2float(hi));
    g_Whi[idx] = hi;
    g_Wlo[idx] = lo;
}

// ---------------------------------------------------------------------------
// S (fp16): S[b][n][w][j*256+l] = xz(b,256+l,(n+6)%7+j-1,w) + xz(b,l,n+j-1,w)
// ---------------------------------------------------------------------------
__global__ void build_s_k(const float* __restrict__ x) {
    extern __shared__ float sx[];  // 512*49 floats
    int b = blockIdx.x;
    const float4* xb = (const float4*)(x + (size_t)b * (CIN * 49));
    for (int i = threadIdx.x; i < CIN * 49 / 4; i += blockDim.x)
        ((float4*)sx)[i] = xb[i];
    __syncthreads();

    size_t base = (size_t)b * (49 * KDIM);
    for (int e = threadIdx.x; e < 49 * KDIM; e += blockDim.x) {
        int c2 = e % KDIM;
        int nw = e / KDIM;
        int n = nw / 7, w = nw - n * 7;
        int j = c2 >> 8, l = c2 & 255;
        int r0 = n + j - 1;
        int n2 = n + 6; if (n2 >= 7) n2 -= 7;
        int r1 = n2 + j - 1;
        float v = 0.f;
        if ((unsigned)r0 < 7u) v += sx[l * 49 + r0 * 7 + w];
        if ((unsigned)r1 < 7u) v += sx[(256 + l) * 49 + r1 * 7 + w];
        g_Shi[base + e] = __float2half_rn(v);
    }
}

// ---------------------------------------------------------------------------
// fp16 GEMM, 2 segments sharing A:  G = Shi*Whi + Shi*Wlo   (= Shi*W)
// Dropped term Slo*W -> predicted norm rel_err ~2.8e-4.
// CTA 128x128, BK=32, 24 chunks, 3-stage cp.async, ONE sync per chunk.
// 8 warps 4(M)x2(N); warp tile 32x64; single fp32 accumulator set.
// Stage: A 128r x 80B (pad 40 halves) = 10240B; Bhi 32r x 272B = 8704B;
//        Blo 8704B  -> 27648B/stage, x3 = 82944B  (2 CTAs/SM).
// ---------------------------------------------------------------------------
#define LDA_S 40
#define LDB_S 136
#define STG_B 27648
#define NCHUNK 24

__global__ __launch_bounds__(256, 2) void gemm_k() {
    extern __shared__ __align__(128) char smem[];
    const uint32_t sb = smem_u32(smem);
    const int tid  = threadIdx.x;
    const int wid  = tid >> 5;
    const int lane = tid & 31;
    const int wm = wid & 3;          // m offset *32
    const int wn = wid >> 2;         // n offset *64

    const size_t m0 = (size_t)blockIdx.y * 128;
    const int    n0 = blockIdx.x * 128;

    const char* Ag  = (const char*)g_Shi + m0 * (KDIM * 2);
    const char* Bhg = (const char*)g_Whi + (size_t)n0 * 2;
    const char* Blg = (const char*)g_Wlo + (size_t)n0 * 2;

    float acc[2][8][4];
#pragma unroll
    for (int mt = 0; mt < 2; mt++)
#pragma unroll
        for (int nt = 0; nt < 8; nt++)
#pragma unroll
            for (int q = 0; q < 4; q++) acc[mt][nt][q] = 0.f;

    auto issue = [&](int kc) {
        const uint32_t st = sb + (kc % 3) * STG_B;
        const int k0 = kc * 32;
        // A: 128 rows x 32 halves (64B); 4x16B per row; 512 chunks / 256 thr
#pragma unroll
        for (int h = 0; h < 2; h++) {
            int c = h * 256 + tid;
            int r = c >> 2, cc = (c & 3) * 8;
            CP16(st + (r * LDA_S + cc) * 2,
                 Ag + (size_t)r * (KDIM * 2) + (k0 + cc) * 2);
        }
        // Bhi/Blo: 32 rows x 128 halves (256B); 16x16B per row; 512 chunks each
#pragma unroll
        for (int h = 0; h < 2; h++) {
            int c = h * 256 + tid;
            int r = c >> 4, cc = (c & 15) * 8;
            size_t gof = (size_t)(k0 + r) * (NDIM * 2) + cc * 2;
            uint32_t sof = (r * LDB_S + cc) * 2;
            CP16(st + 10240 + sof, Bhg + gof);
            CP16(st + 18944 + sof, Blg + gof);
        }
    };

    issue(0); CP_COMMIT();
    issue(1); CP_COMMIT();

    // ldmatrix lane addressing: row = lane&15, col-block = (lane>>4)*8
    const int lr = lane & 15, lc = (lane >> 4) * 8;
    const uint32_t a_base = (uint32_t)((wm * 32 + lr) * LDA_S + lc) * 2;
    const uint32_t b_base = (uint32_t)(lr * LDB_S + wn * 64 + lc) * 2;

    for (int kc = 0; kc < NCHUNK; kc++) {
        CP_WAIT1();
        __syncthreads();
        if (kc + 2 < NCHUNK) issue(kc + 2);
        CP_COMMIT();                 // uniform group numbering

        const uint32_t st = sb + (kc % 3) * STG_B;

#pragma unroll
        for (int ks = 0; ks < 2; ks++) {
            uint32_t af[2][4], bf[4][4];
#pragma unroll
            for (int mt = 0; mt < 2; mt++)
                LDSM_X4(af[mt], st + a_base + (mt * 16 * LDA_S + ks * 16) * 2);
            // --- hi segment ---
#pragma unroll
            for (int nt2 = 0; nt2 < 4; nt2++)
                LDSM_X4_T(bf[nt2], st + 10240 + b_base
                                   + (ks * 16 * LDB_S + nt2 * 16) * 2);
#pragma unroll
            for (int mt = 0; mt < 2; mt++)
#pragma unroll
                for (int nt = 0; nt < 8; nt++)
                    MMA16816(acc[mt][nt], af[mt],
                             bf[nt >> 1][(nt & 1) * 2],
                             bf[nt >> 1][(nt & 1) * 2 + 1]);
            // --- lo segment (same A fragments) ---
#pragma unroll
            for (int nt2 = 0; nt2 < 4; nt2++)
                LDSM_X4_T(bf[nt2], st + 18944 + b_base
                                   + (ks * 16 * LDB_S + nt2 * 16) * 2);
#pragma unroll
            for (int mt = 0; mt < 2; mt++)
#pragma unroll
                for (int nt = 0; nt < 8; nt++)
                    MMA16816(acc[mt][nt], af[mt],
                             bf[nt >> 1][(nt & 1) * 2],
                             bf[nt >> 1][(nt & 1) * 2 + 1]);
        }
    }

    // Write C: d0,d1 -> row g cols 2*tig; d2,d3 -> row g+8
    const int g = lane >> 2, tig = lane & 3;
#pragma unroll
    for (int mt = 0; mt < 2; mt++) {
        size_t mrow = m0 + wm * 32 + mt * 16 + g;
        float* c0 = g_G + mrow * NDIM + n0 + wn * 64 + tig * 2;
        float* c1 = c0 + 8 * NDIM;
#pragma unroll
        for (int nt = 0; nt < 8; nt++) {
            *(float2*)(c0 + nt * 8) = make_float2(acc[mt][nt][0], acc[mt][nt][1]);
            *(float2*)(c1 + nt * 8) = make_float2(acc[mt][nt][2], acc[mt][nt][3]);
        }
    }
}

// ---------------------------------------------------------------------------
// out[b,i,n,p] = sum_k [0 <= p+k-1 < 7] * G[b, n, (p+k+5)%7][k*512+i]
// ---------------------------------------------------------------------------
__global__ void epilogue_k(float* __restrict__ out) {
    __shared__ float sg[7 * NDIM];  // 43 KB
    int b = blockIdx.x / 7;
    int n = blockIdx.x % 7;
    const float4* Gb = (const float4*)(g_G + (size_t)(b * 49 + n * 7) * NDIM);
    for (int i = threadIdx.x; i < 7 * NDIM / 4; i += blockDim.x)
        ((float4*)sg)[i] = Gb[i];
    __syncthreads();

    for (int e = threadIdx.x; e < 512 * 7; e += blockDim.x) {
        int i = e / 7;
        int p = e - i * 7;
        float v = 0.f;
#pragma unroll
        for (int k = 0; k < 3; k++) {
            int q = p + k - 1;
            if ((unsigned)q < 7u) {
                int w = p + k + 5; if (w >= 7) w -= 7;
                v += sg[w * NDIM + (k << 9) + i];
            }
        }
        out[(((size_t)b * 512 + i) * 7 + n) * 7 + p] = v;
    }
}

// ---------------------------------------------------------------------------
extern "C" void kernel_launch(void* const* d_in, const int* in_sizes, int n_in,
                              void* d_out, int out_size) {
    const float* x = (const float*)d_in[0];   // (1024,512,7,7)
    const float* W = (const float*)d_in[1];   // (256,3,3,512)
    float* out = (float*)d_out;               // (1024,512,7,7)

    cudaFuncSetAttribute(build_s_k, cudaFuncAttributeMaxDynamicSharedMemorySize,
                         CIN * 49 * 4);
    cudaFuncSetAttribute(gemm_k, cudaFuncAttributeMaxDynamicSharedMemorySize,
                         3 * STG_B);

    build_w_k<<<(KDIM * NDIM + 255) / 256, 256>>>(W);
    build_s_k<<<BATCH, 256, CIN * 49 * 4>>>(x);

    dim3 grid(NDIM / 128, MDIM / 128);  // (12, 392)
    gemm_k<<<grid, 256, 3 * STG_B>>>();

    epilogue_k<<<BATCH * 7, 256>>>(out);
}